// round 2
// baseline (speedup 1.0000x reference)
#include <cuda_runtime.h>
#include <cuda_bf16.h>

#define NPATH 8192
#define LMAX 32
#define DIN 256
#define EDIM 128
#define HDIM 128
#define G4 512
#define GRP 1024
#define RTOT (NPATH*LMAX)
#define LN_EPS 1e-5f

// ---------------- device scratch (static, no allocation) ----------------
__device__ float g_x[RTOT*EDIM];      // 134 MB: tanh(LN(inputs @ W_in^T))
__device__ float g_gi[(size_t)RTOT*G4]; // 512 MB: x @ Wih^T + bih + bhh
__device__ float g_h[NPATH*HDIM];     // final hidden per path
__device__ float g_logits[NPATH];
__device__ float g_e[NPATH];
__device__ unsigned g_gmax[GRP];
__device__ float g_gsum[GRP];
__device__ float g_cnt[GRP];
__device__ float g_wsum[GRP*HDIM];

__device__ __forceinline__ float sigm(float x) { return 1.0f / (1.0f + expf(-x)); }

__device__ __forceinline__ unsigned enc_f(float f) {
    unsigned u = __float_as_uint(f);
    return (u & 0x80000000u) ? ~u : (u | 0x80000000u);
}
__device__ __forceinline__ float dec_f(unsigned k) {
    return (k & 0x80000000u) ? __uint_as_float(k ^ 0x80000000u) : __uint_as_float(~k);
}

// ---------------- kernel 1: projection + LayerNorm + tanh ----------------
// C[r, e] = tanh(LN(inputs[r,:] @ W_in[e,:]))   r in [0, 262144), e in [0,128)
__global__ void __launch_bounds__(256) k_proj(const float* __restrict__ inp,
                                              const float* __restrict__ W_in,
                                              const float* __restrict__ gamma,
                                              const float* __restrict__ beta) {
    __shared__ float As[64 * 33];
    __shared__ float Bs[32 * 132];
    const int tid = threadIdx.x;
    const int tx = tid & 15, ty = tid >> 4;
    const int r0 = blockIdx.x * 64;

    float acc[4][8];
#pragma unroll
    for (int i = 0; i < 4; i++)
#pragma unroll
        for (int j = 0; j < 8; j++) acc[i][j] = 0.0f;

    for (int kt = 0; kt < 8; kt++) {
        __syncthreads();
        const int kb = kt * 32;
#pragma unroll
        for (int s = 0; s < 8; s++) {
            int idx = tid + s * 256;
            int kk = idx & 31, r = idx >> 5;
            As[r * 33 + kk] = inp[(r0 + r) * DIN + kb + kk];
        }
#pragma unroll
        for (int s = 0; s < 16; s++) {
            int idx = tid + s * 256;
            int kk = idx & 31, e = idx >> 5;
            Bs[kk * 132 + e] = W_in[e * DIN + kb + kk];
        }
        __syncthreads();
#pragma unroll
        for (int kk = 0; kk < 32; kk++) {
            float a[4];
#pragma unroll
            for (int i = 0; i < 4; i++) a[i] = As[(ty * 4 + i) * 33 + kk];
            float4 b0 = *(const float4*)&Bs[kk * 132 + tx * 8];
            float4 b1 = *(const float4*)&Bs[kk * 132 + tx * 8 + 4];
            float b[8] = {b0.x, b0.y, b0.z, b0.w, b1.x, b1.y, b1.z, b1.w};
#pragma unroll
            for (int i = 0; i < 4; i++)
#pragma unroll
                for (int j = 0; j < 8; j++) acc[i][j] += a[i] * b[j];
        }
    }

    float gam[8], bet[8];
#pragma unroll
    for (int j = 0; j < 8; j++) { gam[j] = gamma[tx * 8 + j]; bet[j] = beta[tx * 8 + j]; }

    // LayerNorm: each row's 128 cols live in 16 consecutive lanes (one half-warp)
#pragma unroll
    for (int i = 0; i < 4; i++) {
        float s = 0.0f, q = 0.0f;
#pragma unroll
        for (int j = 0; j < 8; j++) { s += acc[i][j]; q += acc[i][j] * acc[i][j]; }
#pragma unroll
        for (int m = 8; m >= 1; m >>= 1) {
            s += __shfl_xor_sync(0xffffffffu, s, m);
            q += __shfl_xor_sync(0xffffffffu, q, m);
        }
        float mu = s * (1.0f / 128.0f);
        float var = q * (1.0f / 128.0f) - mu * mu;
        float rs = rsqrtf(var + LN_EPS);
        int r = r0 + ty * 4 + i;
        float o[8];
#pragma unroll
        for (int j = 0; j < 8; j++) o[j] = tanhf((acc[i][j] - mu) * rs * gam[j] + bet[j]);
        float4* dst = (float4*)&g_x[r * EDIM + tx * 8];
        dst[0] = make_float4(o[0], o[1], o[2], o[3]);
        dst[1] = make_float4(o[4], o[5], o[6], o[7]);
    }
}

// ---------------- kernel 2: input gate pre-activations ----------------
// g_gi[r, j] = g_x[r,:] @ Wih[j,:] + bih[j] + bhh[j]
__global__ void __launch_bounds__(256) k_gates(const float* __restrict__ Wih,
                                               const float* __restrict__ bih,
                                               const float* __restrict__ bhh) {
    __shared__ float As[64 * 33];
    __shared__ float Bs[32 * 132];
    const int tid = threadIdx.x;
    const int tx = tid & 15, ty = tid >> 4;
    const int r0 = blockIdx.x * 64;
    const int j0 = blockIdx.y * 128;

    float acc[4][8];
#pragma unroll
    for (int i = 0; i < 4; i++)
#pragma unroll
        for (int j = 0; j < 8; j++) acc[i][j] = 0.0f;

    for (int kt = 0; kt < 4; kt++) {
        __syncthreads();
        const int kb = kt * 32;
#pragma unroll
        for (int s = 0; s < 8; s++) {
            int idx = tid + s * 256;
            int kk = idx & 31, r = idx >> 5;
            As[r * 33 + kk] = g_x[(r0 + r) * EDIM + kb + kk];
        }
#pragma unroll
        for (int s = 0; s < 16; s++) {
            int idx = tid + s * 256;
            int kk = idx & 31, j = idx >> 5;
            Bs[kk * 132 + j] = Wih[(j0 + j) * HDIM + kb + kk];
        }
        __syncthreads();
#pragma unroll
        for (int kk = 0; kk < 32; kk++) {
            float a[4];
#pragma unroll
            for (int i = 0; i < 4; i++) a[i] = As[(ty * 4 + i) * 33 + kk];
            float4 b0 = *(const float4*)&Bs[kk * 132 + tx * 8];
            float4 b1 = *(const float4*)&Bs[kk * 132 + tx * 8 + 4];
            float b[8] = {b0.x, b0.y, b0.z, b0.w, b1.x, b1.y, b1.z, b1.w};
#pragma unroll
            for (int i = 0; i < 4; i++)
#pragma unroll
                for (int j = 0; j < 8; j++) acc[i][j] += a[i] * b[j];
        }
    }

    float bs[8];
#pragma unroll
    for (int j = 0; j < 8; j++) {
        int jj = j0 + tx * 8 + j;
        bs[j] = bih[jj] + bhh[jj];
    }
#pragma unroll
    for (int i = 0; i < 4; i++) {
        size_t r = (size_t)(r0 + ty * 4 + i);
        float4* dst = (float4*)&g_gi[r * G4 + j0 + tx * 8];
        dst[0] = make_float4(acc[i][0] + bs[0], acc[i][1] + bs[1], acc[i][2] + bs[2], acc[i][3] + bs[3]);
        dst[1] = make_float4(acc[i][4] + bs[4], acc[i][5] + bs[5], acc[i][6] + bs[6], acc[i][7] + bs[7]);
    }
}

// ---------------- kernel 3: LSTM recurrence ----------------
// 32 paths per block; h in smem, c in registers; Whh streamed from L2.
__global__ void __launch_bounds__(256, 2) k_lstm(const float* __restrict__ Whh,
                                                 const int* __restrict__ lens) {
    extern __shared__ float sm[];
    float* hs = sm;                 // 32*129
    float* gs = sm + 32 * 129;      // 32*516
    float* Bs = gs + 32 * 516;      // 32*132
    __shared__ int ln_s[32];

    const int tid = threadIdx.x;
    const int tx = tid & 15, ty = tid >> 4;
    const int n0 = blockIdx.x * 32;

#pragma unroll
    for (int s = 0; s < 16; s++) {
        int idx = tid + s * 256;
        int n = idx >> 7, k = idx & 127;
        hs[n * 129 + k] = 0.0f;
    }
    if (tid < 32) ln_s[tid] = lens[n0 + tid];
    float c_reg[16];
#pragma unroll
    for (int s = 0; s < 16; s++) c_reg[s] = 0.0f;
    __syncthreads();

    for (int t = 0; t < LMAX; t++) {
        // gate GEMMs: r = hs @ Whh^T for each of the 4 gate blocks (128 cols each)
        for (int q = 0; q < 4; q++) {
            float acc[2][8];
#pragma unroll
            for (int i = 0; i < 2; i++)
#pragma unroll
                for (int j = 0; j < 8; j++) acc[i][j] = 0.0f;

            for (int kt = 0; kt < 4; kt++) {
                __syncthreads();
                const int kb = kt * 32;
#pragma unroll
                for (int s = 0; s < 16; s++) {
                    int idx = tid + s * 256;
                    int kk = idx & 31, j = idx >> 5;
                    Bs[kk * 132 + j] = Whh[(q * 128 + j) * HDIM + kb + kk];
                }
                __syncthreads();
#pragma unroll
                for (int kk = 0; kk < 32; kk++) {
                    float a0 = hs[(ty * 2) * 129 + kb + kk];
                    float a1 = hs[(ty * 2 + 1) * 129 + kb + kk];
                    float4 b0 = *(const float4*)&Bs[kk * 132 + tx * 8];
                    float4 b1 = *(const float4*)&Bs[kk * 132 + tx * 8 + 4];
                    float b[8] = {b0.x, b0.y, b0.z, b0.w, b1.x, b1.y, b1.z, b1.w};
#pragma unroll
                    for (int j = 0; j < 8; j++) {
                        acc[0][j] += a0 * b[j];
                        acc[1][j] += a1 * b[j];
                    }
                }
            }
#pragma unroll
            for (int i = 0; i < 2; i++) {
                float4* d = (float4*)&gs[(ty * 2 + i) * 516 + q * 128 + tx * 8];
                d[0] = make_float4(acc[i][0], acc[i][1], acc[i][2], acc[i][3]);
                d[1] = make_float4(acc[i][4], acc[i][5], acc[i][6], acc[i][7]);
            }
        }
        __syncthreads();
        // cell update
#pragma unroll
        for (int s = 0; s < 16; s++) {
            int idx = tid + s * 256;
            int n = idx >> 7, k = idx & 127;
            size_t base = ((size_t)(n0 + n) * LMAX + t) * G4 + k;
            float xi = g_gi[base] + gs[n * 516 + k];
            float xf = g_gi[base + 128] + gs[n * 516 + 128 + k];
            float xg = g_gi[base + 256] + gs[n * 516 + 256 + k];
            float xo = g_gi[base + 384] + gs[n * 516 + 384 + k];
            if (t < ln_s[n]) {
                float cn = sigm(xf) * c_reg[s] + sigm(xi) * tanhf(xg);
                c_reg[s] = cn;
                hs[n * 129 + k] = sigm(xo) * tanhf(cn);
            }
        }
        __syncthreads();
    }

#pragma unroll
    for (int s = 0; s < 16; s++) {
        int idx = tid + s * 256;
        int n = idx >> 7, k = idx & 127;
        g_h[(n0 + n) * HDIM + k] = hs[n * 129 + k];
    }
}

// ---------------- kernel 4a: zero/init accumulators ----------------
__global__ void k_init() {
    int i = blockIdx.x * blockDim.x + threadIdx.x;
    if (i < GRP * HDIM) g_wsum[i] = 0.0f;
    if (i < GRP) {
        g_gsum[i] = 0.0f;
        g_cnt[i] = 0.0f;
        g_gmax[i] = 0u;  // < enc(any finite float)
    }
}

// ---------------- kernel 4b: attention logits + segment max ----------------
__global__ void __launch_bounds__(256) k_logits(const float* __restrict__ ap,
                                                const int* __restrict__ seg) {
    int w = threadIdx.x >> 5, lane = threadIdx.x & 31;
    int n = blockIdx.x * 8 + w;
    float s = 0.0f;
#pragma unroll
    for (int q = 0; q < 4; q++) s += g_h[n * HDIM + lane + 32 * q] * ap[lane + 32 * q];
#pragma unroll
    for (int m = 16; m >= 1; m >>= 1) s += __shfl_xor_sync(0xffffffffu, s, m);
    if (lane == 0) {
        g_logits[n] = s;
        atomicMax(&g_gmax[seg[n]], enc_f(s));
    }
}

// ---------------- kernel 4c: exp + segment sum + count ----------------
__global__ void __launch_bounds__(256) k_expsum(const int* __restrict__ seg) {
    int n = blockIdx.x * 256 + threadIdx.x;
    int g = seg[n];
    float e = expf(g_logits[n] - dec_f(g_gmax[g]));
    g_e[n] = e;
    atomicAdd(&g_gsum[g], e);
    atomicAdd(&g_cnt[g], 1.0f);
}

// ---------------- kernel 4d: weighted hidden sum per group ----------------
__global__ void __launch_bounds__(256) k_wsum(const int* __restrict__ seg) {
    int w = threadIdx.x >> 5, lane = threadIdx.x & 31;
    int n = blockIdx.x * 8 + w;
    float e = g_e[n];
    int g = seg[n];
#pragma unroll
    for (int q = 0; q < 4; q++)
        atomicAdd(&g_wsum[g * HDIM + lane + 32 * q], e * g_h[n * HDIM + lane + 32 * q]);
}

// ---------------- kernel 5: head (code -> code_vectors -> outputs) ----------------
__global__ void __launch_bounds__(256) k_head(const float* __restrict__ W_out,
                                              const float* __restrict__ W_cls,
                                              const float* __restrict__ ap,
                                              float* __restrict__ out,
                                              int out_size) {
    __shared__ float cs[16 * 128];
    __shared__ float cvs[16 * 128];
    const int tid = threadIdx.x;
    const int g0 = blockIdx.x * 16;
    const bool full = (out_size >= 2048 + GRP * HDIM + HDIM);

#pragma unroll
    for (int s = 0; s < 8; s++) {
        int idx = tid + s * 256;
        int gg = idx >> 7, k = idx & 127;
        int gi = g0 + gg;
        cs[gg * 128 + k] = g_wsum[gi * HDIM + k] / (g_gsum[gi] * g_cnt[gi]);
    }
    __syncthreads();

    int row = tid >> 4;
    int c0 = (tid & 15) * 8;
    float acc[8];
#pragma unroll
    for (int j = 0; j < 8; j++) acc[j] = 0.0f;
    for (int k = 0; k < 128; k++) {
        float a = cs[row * 128 + k];
#pragma unroll
        for (int j = 0; j < 8; j++) acc[j] += a * W_out[(c0 + j) * 128 + k];
    }
#pragma unroll
    for (int j = 0; j < 8; j++) {
        cvs[row * 128 + c0 + j] = acc[j];
        if (full) out[2048 + (g0 + row) * 128 + c0 + j] = acc[j];
    }
    __syncthreads();

    if (tid < 32) {
        int r = tid >> 1, c = tid & 1;
        float s = 0.0f;
        for (int k = 0; k < 128; k++) s += cvs[r * 128 + k] * W_cls[c * 128 + k];
        out[(g0 + r) * 2 + c] = s;
    }
    if (full && blockIdx.x == 0 && tid < 128) out[2048 + GRP * HDIM + tid] = ap[tid];
}

// ---------------- launch ----------------
extern "C" void kernel_launch(void* const* d_in, const int* in_sizes, int n_in,
                              void* d_out, int out_size) {
    const float* inputs = (const float*)d_in[0];
    const int* lens     = (const int*)d_in[1];
    const int* seg      = (const int*)d_in[2];
    const float* W_in   = (const float*)d_in[3];
    const float* gamma  = (const float*)d_in[4];
    const float* beta   = (const float*)d_in[5];
    const float* Wih    = (const float*)d_in[6];
    const float* Whh    = (const float*)d_in[7];
    const float* bih    = (const float*)d_in[8];
    const float* bhh    = (const float*)d_in[9];
    const float* ap     = (const float*)d_in[10];
    const float* W_out  = (const float*)d_in[11];
    const float* W_cls  = (const float*)d_in[12];
    float* out = (float*)d_out;

    const int lstm_smem = (32 * 129 + 32 * 516 + 32 * 132) * 4;  // 99456 B
    cudaFuncSetAttribute(k_lstm, cudaFuncAttributeMaxDynamicSharedMemorySize, lstm_smem);

    k_proj<<<RTOT / 64, 256>>>(inputs, W_in, gamma, beta);
    k_gates<<<dim3(RTOT / 64, 4), 256>>>(Wih, bih, bhh);
    k_lstm<<<NPATH / 32, 256, lstm_smem>>>(Whh, lens);
    k_init<<<(GRP * HDIM + 255) / 256, 256>>>();
    k_logits<<<NPATH / 8, 256>>>(ap, seg);
    k_expsum<<<NPATH / 256, 256>>>(seg);
    k_wsum<<<NPATH / 8, 256>>>(seg);
    k_head<<<GRP / 16, 256>>>(W_out, W_cls, ap, out, out_size);
}

// round 3
// speedup vs baseline: 1.8098x; 1.8098x over previous
#include <cuda_runtime.h>
#include <cuda_bf16.h>

#define NPATH 8192
#define LMAX 32
#define DIN 256
#define EDIM 128
#define HDIM 128
#define G4 512
#define GRP 1024
#define RTOT (NPATH*LMAX)
#define LN_EPS 1e-5f

// ---------------- device scratch (static, no allocation) ----------------
__device__ float g_gi[(size_t)RTOT*G4]; // 512 MB: x @ Wih^T + bih + bhh (valid t only)
__device__ float g_WhhT[HDIM*G4];       // Whh transposed: [k][j]
__device__ float g_h[NPATH*HDIM];
__device__ float g_logits[NPATH];
__device__ float g_e[NPATH];
__device__ unsigned g_gmax[GRP];
__device__ float g_gsum[GRP];
__device__ float g_cnt[GRP];
__device__ float g_wsum[GRP*HDIM];

__device__ __forceinline__ float sigm(float x) { return 1.0f / (1.0f + expf(-x)); }

__device__ __forceinline__ unsigned enc_f(float f) {
    unsigned u = __float_as_uint(f);
    return (u & 0x80000000u) ? ~u : (u | 0x80000000u);
}
__device__ __forceinline__ float dec_f(unsigned k) {
    return (k & 0x80000000u) ? __uint_as_float(k ^ 0x80000000u) : __uint_as_float(~k);
}

// ---------------- kernel 0: transpose Whh once ----------------
__global__ void __launch_bounds__(256) k_tw(const float* __restrict__ Whh) {
    int idx = blockIdx.x * 256 + threadIdx.x;   // 65536 total
    int j = idx >> 7, k = idx & 127;
    g_WhhT[k * G4 + j] = Whh[j * HDIM + k];
}

// ---------------- kernel 1: fused projection+LN+tanh + input-gate GEMM ----------------
// block = 64 rows = 2 paths. Phase1: x = tanh(LN(inp @ W_in^T)) -> smem Xs.
// Phase2: gi = Xs @ Wih^T + bih + bhh -> g_gi (valid rows only).
// Warp w owns rows 8w..8w+7 (t = 8w&31 .. within one path) -> warp-level skip.
__global__ void __launch_bounds__(256, 3) k_fp(const float* __restrict__ inp,
                                               const float* __restrict__ W_in,
                                               const float* __restrict__ gamma,
                                               const float* __restrict__ beta,
                                               const float* __restrict__ Wih,
                                               const float* __restrict__ bih,
                                               const float* __restrict__ bhh,
                                               const int* __restrict__ lens) {
    extern __shared__ float sm[];
    float* As = sm;                 // 64*33
    float* Bs = sm + 64 * 33;       // 32*132
    float* Xs = Bs + 32 * 132;      // 64*132
    __shared__ int len2[2];

    const int tid = threadIdx.x;
    const int tx = tid & 15, ty = tid >> 4;
    const int w = tid >> 5;
    const int r0 = blockIdx.x * 64;

    if (tid < 2) len2[tid] = lens[blockIdx.x * 2 + tid];
    __syncthreads();
    const bool wactive = ((8 * w) & 31) < len2[w >> 2];

    // ---- phase 1: x = tanh(LN(inp @ W_in^T)) ----
    float acc[4][8];
#pragma unroll
    for (int i = 0; i < 4; i++)
#pragma unroll
        for (int j = 0; j < 8; j++) acc[i][j] = 0.0f;

    for (int kt = 0; kt < 8; kt++) {
        __syncthreads();
        const int kb = kt * 32;
#pragma unroll
        for (int s = 0; s < 8; s++) {
            int idx = tid + s * 256;
            int kk = idx & 31, r = idx >> 5;
            int t = r & 31, p = r >> 5;
            As[r * 33 + kk] = (t < len2[p]) ? inp[(size_t)(r0 + r) * DIN + kb + kk] : 0.0f;
        }
#pragma unroll
        for (int s = 0; s < 16; s++) {
            int idx = tid + s * 256;
            int kk = idx & 31, e = idx >> 5;
            Bs[kk * 132 + e] = W_in[e * DIN + kb + kk];
        }
        __syncthreads();
        if (wactive) {
#pragma unroll 8
            for (int kk = 0; kk < 32; kk++) {
                float a[4];
#pragma unroll
                for (int i = 0; i < 4; i++) a[i] = As[(ty * 4 + i) * 33 + kk];
                float4 b0 = *(const float4*)&Bs[kk * 132 + tx * 8];
                float4 b1 = *(const float4*)&Bs[kk * 132 + tx * 8 + 4];
                float b[8] = {b0.x, b0.y, b0.z, b0.w, b1.x, b1.y, b1.z, b1.w};
#pragma unroll
                for (int i = 0; i < 4; i++)
#pragma unroll
                    for (int j = 0; j < 8; j++) acc[i][j] += a[i] * b[j];
            }
        }
    }

    if (wactive) {
        float gam[8], bet[8];
#pragma unroll
        for (int j = 0; j < 8; j++) { gam[j] = gamma[tx * 8 + j]; bet[j] = beta[tx * 8 + j]; }
#pragma unroll
        for (int i = 0; i < 4; i++) {
            float s = 0.0f, q = 0.0f;
#pragma unroll
            for (int j = 0; j < 8; j++) { s += acc[i][j]; q += acc[i][j] * acc[i][j]; }
#pragma unroll
            for (int m = 8; m >= 1; m >>= 1) {
                s += __shfl_xor_sync(0xffffffffu, s, m);
                q += __shfl_xor_sync(0xffffffffu, q, m);
            }
            float mu = s * (1.0f / 128.0f);
            float var = q * (1.0f / 128.0f) - mu * mu;
            float rs = rsqrtf(var + LN_EPS);
            int r = ty * 4 + i;
            float o[8];
#pragma unroll
            for (int j = 0; j < 8; j++) o[j] = tanhf((acc[i][j] - mu) * rs * gam[j] + bet[j]);
            float4* dst = (float4*)&Xs[r * 132 + tx * 8];
            dst[0] = make_float4(o[0], o[1], o[2], o[3]);
            dst[1] = make_float4(o[4], o[5], o[6], o[7]);
        }
    }

    // ---- phase 2: gi = Xs @ Wih^T + b ----
    for (int j0t = 0; j0t < 4; j0t++) {
        const int j0 = j0t * 128;
        float acc2[4][8];
#pragma unroll
        for (int i = 0; i < 4; i++)
#pragma unroll
            for (int j = 0; j < 8; j++) acc2[i][j] = 0.0f;

        for (int kt = 0; kt < 4; kt++) {
            __syncthreads();
            const int kb = kt * 32;
#pragma unroll
            for (int s = 0; s < 16; s++) {
                int idx = tid + s * 256;
                int kk = idx & 31, j = idx >> 5;
                Bs[kk * 132 + j] = Wih[(j0 + j) * HDIM + kb + kk];
            }
            __syncthreads();
            if (wactive) {
#pragma unroll 8
                for (int kk = 0; kk < 32; kk++) {
                    float a[4];
#pragma unroll
                    for (int i = 0; i < 4; i++) a[i] = Xs[(ty * 4 + i) * 132 + kb + kk];
                    float4 b0 = *(const float4*)&Bs[kk * 132 + tx * 8];
                    float4 b1 = *(const float4*)&Bs[kk * 132 + tx * 8 + 4];
                    float b[8] = {b0.x, b0.y, b0.z, b0.w, b1.x, b1.y, b1.z, b1.w};
#pragma unroll
                    for (int i = 0; i < 4; i++)
#pragma unroll
                        for (int j = 0; j < 8; j++) acc2[i][j] += a[i] * b[j];
                }
            }
        }
        if (wactive) {
            float bs[8];
#pragma unroll
            for (int j = 0; j < 8; j++) {
                int jj = j0 + tx * 8 + j;
                bs[j] = bih[jj] + bhh[jj];
            }
#pragma unroll
            for (int i = 0; i < 4; i++) {
                int r = ty * 4 + i;
                int t = r & 31, p = r >> 5;
                if (t < len2[p]) {
                    size_t base = ((size_t)(blockIdx.x * 2 + p) * LMAX + t) * G4 + j0 + tx * 8;
                    float4* dst = (float4*)&g_gi[base];
                    dst[0] = make_float4(acc2[i][0] + bs[0], acc2[i][1] + bs[1],
                                         acc2[i][2] + bs[2], acc2[i][3] + bs[3]);
                    dst[1] = make_float4(acc2[i][4] + bs[4], acc2[i][5] + bs[5],
                                         acc2[i][6] + bs[6], acc2[i][7] + bs[7]);
                }
            }
        }
    }
}

// ---------------- kernel 2: LSTM recurrence ----------------
// 32 paths/block, 256 threads: ty=tid>>5 owns 4 rows, tx=tid&31 owns 4 cols per gate.
// All 4 gates accumulated in registers; cell update in registers; h exchange intra-warp.
__global__ void __launch_bounds__(256, 2) k_lstm(const int* __restrict__ lens) {
    extern __shared__ float sm[];
    float* hs = sm;                 // 32*132
    float* Bs = sm + 32 * 132;      // 32*520
    __shared__ int ln_s[32];
    __shared__ int maxlen_s;

    const int tid = threadIdx.x;
    const int tx = tid & 31, ty = tid >> 5;
    const int n0 = blockIdx.x * 32;

#pragma unroll
    for (int s = 0; s < 16; s++) {
        int idx = tid + s * 256;
        int n = idx >> 7, k = idx & 127;
        hs[n * 132 + k] = 0.0f;
    }
    if (tid < 32) {
        int l = lens[n0 + tid];
        ln_s[tid] = l;
#pragma unroll
        for (int m = 16; m >= 1; m >>= 1) l = max(l, __shfl_xor_sync(0xffffffffu, l, m));
        if (tid == 0) maxlen_s = l;
    }
    __syncthreads();

    int myln[4];
    int mymax = 0;
#pragma unroll
    for (int i = 0; i < 4; i++) { myln[i] = ln_s[4 * ty + i]; mymax = max(mymax, myln[i]); }
    const int blkmax = maxlen_s;

    float c[4][4];
#pragma unroll
    for (int i = 0; i < 4; i++)
#pragma unroll
        for (int j = 0; j < 4; j++) c[i][j] = 0.0f;

    for (int t = 0; t < blkmax; t++) {
        float acc[4][4][4];
#pragma unroll
        for (int i = 0; i < 4; i++)
#pragma unroll
            for (int q = 0; q < 4; q++)
#pragma unroll
                for (int j = 0; j < 4; j++) acc[i][q][j] = 0.0f;

        const bool active = (t < mymax);

        for (int kt = 0; kt < 4; kt++) {
            __syncthreads();
#pragma unroll
            for (int s = 0; s < 16; s++) {
                int f4 = tid + s * 256;          // 0..4095 float4s
                int kk = f4 >> 7;
                int col = (f4 & 127) * 4;
                *(float4*)&Bs[kk * 520 + col] =
                    *(const float4*)&g_WhhT[(kt * 32 + kk) * G4 + col];
            }
            __syncthreads();
            if (active) {
                const int kb = kt * 32;
#pragma unroll 8
                for (int kk = 0; kk < 32; kk++) {
                    float a[4];
#pragma unroll
                    for (int i = 0; i < 4; i++) a[i] = hs[(4 * ty + i) * 132 + kb + kk];
#pragma unroll
                    for (int q = 0; q < 4; q++) {
                        float4 b = *(const float4*)&Bs[kk * 520 + q * 128 + tx * 4];
#pragma unroll
                        for (int i = 0; i < 4; i++) {
                            acc[i][q][0] += a[i] * b.x;
                            acc[i][q][1] += a[i] * b.y;
                            acc[i][q][2] += a[i] * b.z;
                            acc[i][q][3] += a[i] * b.w;
                        }
                    }
                }
            }
        }

        if (active) {
#pragma unroll
            for (int i = 0; i < 4; i++) {
                int n = 4 * ty + i;
                if (t < myln[i]) {
                    size_t base = ((size_t)(n0 + n) * LMAX + t) * G4 + tx * 4;
                    float4 gi = *(const float4*)&g_gi[base];
                    float4 gf = *(const float4*)&g_gi[base + 128];
                    float4 gg = *(const float4*)&g_gi[base + 256];
                    float4 go = *(const float4*)&g_gi[base + 384];
                    float xi[4] = {gi.x + acc[i][0][0], gi.y + acc[i][0][1], gi.z + acc[i][0][2], gi.w + acc[i][0][3]};
                    float xf[4] = {gf.x + acc[i][1][0], gf.y + acc[i][1][1], gf.z + acc[i][1][2], gf.w + acc[i][1][3]};
                    float xg[4] = {gg.x + acc[i][2][0], gg.y + acc[i][2][1], gg.z + acc[i][2][2], gg.w + acc[i][2][3]};
                    float xo[4] = {go.x + acc[i][3][0], go.y + acc[i][3][1], go.z + acc[i][3][2], go.w + acc[i][3][3]};
                    float h4[4];
#pragma unroll
                    for (int j = 0; j < 4; j++) {
                        float cn = sigm(xf[j]) * c[i][j] + sigm(xi[j]) * tanhf(xg[j]);
                        c[i][j] = cn;
                        h4[j] = sigm(xo[j]) * tanhf(cn);
                    }
                    *(float4*)&hs[n * 132 + tx * 4] = make_float4(h4[0], h4[1], h4[2], h4[3]);
                }
            }
            __syncwarp();
        }
    }

    __syncwarp();
#pragma unroll
    for (int i = 0; i < 4; i++) {
        int n = 4 * ty + i;
        *(float4*)&g_h[(size_t)(n0 + n) * HDIM + tx * 4] = *(const float4*)&hs[n * 132 + tx * 4];
    }
}

// ---------------- kernel 3a: init accumulators ----------------
__global__ void k_init() {
    int i = blockIdx.x * blockDim.x + threadIdx.x;
    if (i < GRP * HDIM) g_wsum[i] = 0.0f;
    if (i < GRP) {
        g_gsum[i] = 0.0f;
        g_cnt[i] = 0.0f;
        g_gmax[i] = 0u;
    }
}

// ---------------- kernel 3b: attention logits + segment max ----------------
__global__ void __launch_bounds__(256) k_logits(const float* __restrict__ ap,
                                                const int* __restrict__ seg) {
    int w = threadIdx.x >> 5, lane = threadIdx.x & 31;
    int n = blockIdx.x * 8 + w;
    float s = 0.0f;
#pragma unroll
    for (int q = 0; q < 4; q++) s += g_h[n * HDIM + lane + 32 * q] * ap[lane + 32 * q];
#pragma unroll
    for (int m = 16; m >= 1; m >>= 1) s += __shfl_xor_sync(0xffffffffu, s, m);
    if (lane == 0) {
        g_logits[n] = s;
        atomicMax(&g_gmax[seg[n]], enc_f(s));
    }
}

// ---------------- kernel 3c: exp + segment sum + count ----------------
__global__ void __launch_bounds__(256) k_expsum(const int* __restrict__ seg) {
    int n = blockIdx.x * 256 + threadIdx.x;
    int g = seg[n];
    float e = expf(g_logits[n] - dec_f(g_gmax[g]));
    g_e[n] = e;
    atomicAdd(&g_gsum[g], e);
    atomicAdd(&g_cnt[g], 1.0f);
}

// ---------------- kernel 3d: weighted hidden sum per group ----------------
__global__ void __launch_bounds__(256) k_wsum(const int* __restrict__ seg) {
    int w = threadIdx.x >> 5, lane = threadIdx.x & 31;
    int n = blockIdx.x * 8 + w;
    float e = g_e[n];
    int g = seg[n];
#pragma unroll
    for (int q = 0; q < 4; q++)
        atomicAdd(&g_wsum[g * HDIM + lane + 32 * q], e * g_h[n * HDIM + lane + 32 * q]);
}

// ---------------- kernel 4: head ----------------
__global__ void __launch_bounds__(256) k_head(const float* __restrict__ W_out,
                                              const float* __restrict__ W_cls,
                                              const float* __restrict__ ap,
                                              float* __restrict__ out,
                                              int out_size) {
    __shared__ float cs[16 * 128];
    __shared__ float cvs[16 * 128];
    const int tid = threadIdx.x;
    const int g0 = blockIdx.x * 16;
    const bool full = (out_size >= 2048 + GRP * HDIM + HDIM);

#pragma unroll
    for (int s = 0; s < 8; s++) {
        int idx = tid + s * 256;
        int gg = idx >> 7, k = idx & 127;
        int gi = g0 + gg;
        cs[gg * 128 + k] = g_wsum[gi * HDIM + k] / (g_gsum[gi] * g_cnt[gi]);
    }
    __syncthreads();

    int row = tid >> 4;
    int c0 = (tid & 15) * 8;
    float acc[8];
#pragma unroll
    for (int j = 0; j < 8; j++) acc[j] = 0.0f;
    for (int k = 0; k < 128; k++) {
        float a = cs[row * 128 + k];
#pragma unroll
        for (int j = 0; j < 8; j++) acc[j] += a * W_out[(c0 + j) * 128 + k];
    }
#pragma unroll
    for (int j = 0; j < 8; j++) {
        cvs[row * 128 + c0 + j] = acc[j];
        if (full) out[2048 + (g0 + row) * 128 + c0 + j] = acc[j];
    }
    __syncthreads();

    if (tid < 32) {
        int r = tid >> 1, c = tid & 1;
        float s = 0.0f;
        for (int k = 0; k < 128; k++) s += cvs[r * 128 + k] * W_cls[c * 128 + k];
        out[(g0 + r) * 2 + c] = s;
    }
    if (full && blockIdx.x == 0 && tid < 128) out[2048 + GRP * HDIM + tid] = ap[tid];
}

// ---------------- launch ----------------
extern "C" void kernel_launch(void* const* d_in, const int* in_sizes, int n_in,
                              void* d_out, int out_size) {
    const float* inputs = (const float*)d_in[0];
    const int* lens     = (const int*)d_in[1];
    const int* seg      = (const int*)d_in[2];
    const float* W_in   = (const float*)d_in[3];
    const float* gamma  = (const float*)d_in[4];
    const float* beta   = (const float*)d_in[5];
    const float* Wih    = (const float*)d_in[6];
    const float* Whh    = (const float*)d_in[7];
    const float* bih    = (const float*)d_in[8];
    const float* bhh    = (const float*)d_in[9];
    const float* ap     = (const float*)d_in[10];
    const float* W_out  = (const float*)d_in[11];
    const float* W_cls  = (const float*)d_in[12];
    float* out = (float*)d_out;

    const int fp_smem   = (64 * 33 + 32 * 132 + 64 * 132) * 4;   // 59136 B
    const int lstm_smem = (32 * 132 + 32 * 520) * 4;             // 83456 B
    cudaFuncSetAttribute(k_fp, cudaFuncAttributeMaxDynamicSharedMemorySize, fp_smem);
    cudaFuncSetAttribute(k_lstm, cudaFuncAttributeMaxDynamicSharedMemorySize, lstm_smem);

    k_tw<<<256, 256>>>(Whh);
    k_fp<<<RTOT / 64, 256, fp_smem>>>(inputs, W_in, gamma, beta, Wih, bih, bhh, lens);
    k_lstm<<<NPATH / 32, 256, lstm_smem>>>(lens);
    k_init<<<(GRP * HDIM + 255) / 256, 256>>>();
    k_logits<<<NPATH / 8, 256>>>(ap, seg);
    k_expsum<<<NPATH / 256, 256>>>(seg);
    k_wsum<<<NPATH / 8, 256>>>(seg);
    k_head<<<GRP / 16, 256>>>(W_out, W_cls, ap, out, out_size);
}

// round 5
// speedup vs baseline: 1.9306x; 1.0668x over previous
#include <cuda_runtime.h>
#include <cuda_bf16.h>
#include <cstdint>

#define NPATH 8192
#define LMAX 32
#define DIN 256
#define EDIM 128
#define HDIM 128
#define G4 512
#define GRP 1024
#define RTOT (NPATH*LMAX)
#define LN_EPS 1e-5f

typedef unsigned long long ull;

// ---------------- device scratch (static, no allocation) ----------------
__device__ float g_gi[(size_t)RTOT*G4]; // 512 MB: x @ Wih^T + bih + bhh (valid t only)
__device__ float g_WhhT[HDIM*G4];       // Whh transposed: [k][j]
__device__ float g_h[NPATH*HDIM];
__device__ float g_logits[NPATH];
__device__ float g_e[NPATH];
__device__ unsigned g_gmax[GRP];
__device__ float g_gsum[GRP];
__device__ float g_cnt[GRP];
__device__ float g_wsum[GRP*HDIM];

__device__ __forceinline__ float sigm(float x) { return 1.0f / (1.0f + expf(-x)); }

__device__ __forceinline__ unsigned enc_f(float f) {
    unsigned u = __float_as_uint(f);
    return (u & 0x80000000u) ? ~u : (u | 0x80000000u);
}
__device__ __forceinline__ float dec_f(unsigned k) {
    return (k & 0x80000000u) ? __uint_as_float(k ^ 0x80000000u) : __uint_as_float(~k);
}

// ---------------- packed f32x2 helpers ----------------
__device__ __forceinline__ ull fma2(ull a, ull b, ull c) {
    ull d;
    asm("fma.rn.f32x2 %0, %1, %2, %3;" : "=l"(d) : "l"(a), "l"(b), "l"(c));
    return d;
}
__device__ __forceinline__ ull pack2(float x, float y) {
    ull d;
    asm("mov.b64 %0, {%1, %2};" : "=l"(d) : "f"(x), "f"(y));
    return d;
}
__device__ __forceinline__ float2 unpack2(ull v) {
    float2 r;
    asm("mov.b64 {%0, %1}, %2;" : "=f"(r.x), "=f"(r.y) : "l"(v));
    return r;
}

// ---------------- kernel 0: transpose Whh once ----------------
__global__ void __launch_bounds__(256) k_tw(const float* __restrict__ Whh) {
    int idx = blockIdx.x * 256 + threadIdx.x;   // 65536 total
    int j = idx >> 7, k = idx & 127;
    g_WhhT[k * G4 + j] = Whh[j * HDIM + k];
}

// ---------------- kernel 1: fused projection+LN+tanh + input-gate GEMM ----------------
// block = 64 rows = 2 paths. Phase1: x = tanh(LN(inp @ W_in^T)) -> smem Xs.
// Phase2: gi = Xs @ Wih^T + bih + bhh -> g_gi (valid rows only).
// Warp w owns rows 8w..8w+7 -> warp-level skip. Inner loops: fma.rn.f32x2.
__global__ void __launch_bounds__(256, 3) k_fp(const float* __restrict__ inp,
                                               const float* __restrict__ W_in,
                                               const float* __restrict__ gamma,
                                               const float* __restrict__ beta,
                                               const float* __restrict__ Wih,
                                               const float* __restrict__ bih,
                                               const float* __restrict__ bhh,
                                               const int* __restrict__ lens) {
    extern __shared__ float sm[];
    float* As = sm;                 // 64*33
    float* Bs = sm + 64 * 33;       // 32*132
    float* Xs = Bs + 32 * 132;      // 64*132
    __shared__ int len2[2];

    const int tid = threadIdx.x;
    const int tx = tid & 15, ty = tid >> 4;
    const int w = tid >> 5;
    const int r0 = blockIdx.x * 64;

    if (tid < 2) len2[tid] = lens[blockIdx.x * 2 + tid];
    __syncthreads();
    const bool wactive = ((8 * w) & 31) < len2[w >> 2];

    // ---- phase 1: x = tanh(LN(inp @ W_in^T)) ----
    ull acc[4][4];
#pragma unroll
    for (int i = 0; i < 4; i++)
#pragma unroll
        for (int j = 0; j < 4; j++) acc[i][j] = 0ull;

    for (int kt = 0; kt < 8; kt++) {
        __syncthreads();
        const int kb = kt * 32;
#pragma unroll
        for (int s = 0; s < 8; s++) {
            int idx = tid + s * 256;
            int kk = idx & 31, r = idx >> 5;
            int t = r & 31, p = r >> 5;
            As[r * 33 + kk] = (t < len2[p]) ? inp[(size_t)(r0 + r) * DIN + kb + kk] : 0.0f;
        }
#pragma unroll
        for (int s = 0; s < 16; s++) {
            int idx = tid + s * 256;
            int kk = idx & 31, e = idx >> 5;
            Bs[kk * 132 + e] = W_in[e * DIN + kb + kk];
        }
        __syncthreads();
        if (wactive) {
#pragma unroll 8
            for (int kk = 0; kk < 32; kk++) {
                ull a2[4];
#pragma unroll
                for (int i = 0; i < 4; i++) {
                    float a = As[(ty * 4 + i) * 33 + kk];
                    a2[i] = pack2(a, a);
                }
                ulonglong2 b01 = *(const ulonglong2*)&Bs[kk * 132 + tx * 8];
                ulonglong2 b23 = *(const ulonglong2*)&Bs[kk * 132 + tx * 8 + 4];
#pragma unroll
                for (int i = 0; i < 4; i++) {
                    acc[i][0] = fma2(a2[i], b01.x, acc[i][0]);
                    acc[i][1] = fma2(a2[i], b01.y, acc[i][1]);
                    acc[i][2] = fma2(a2[i], b23.x, acc[i][2]);
                    acc[i][3] = fma2(a2[i], b23.y, acc[i][3]);
                }
            }
        }
    }

    if (wactive) {
        float gam[8], bet[8];
#pragma unroll
        for (int j = 0; j < 8; j++) { gam[j] = gamma[tx * 8 + j]; bet[j] = beta[tx * 8 + j]; }
#pragma unroll
        for (int i = 0; i < 4; i++) {
            float v[8];
#pragma unroll
            for (int p = 0; p < 4; p++) {
                float2 u = unpack2(acc[i][p]);
                v[2 * p] = u.x; v[2 * p + 1] = u.y;
            }
            float s = 0.0f, q = 0.0f;
#pragma unroll
            for (int j = 0; j < 8; j++) { s += v[j]; q += v[j] * v[j]; }
#pragma unroll
            for (int m = 8; m >= 1; m >>= 1) {
                s += __shfl_xor_sync(0xffffffffu, s, m);
                q += __shfl_xor_sync(0xffffffffu, q, m);
            }
            float mu = s * (1.0f / 128.0f);
            float var = q * (1.0f / 128.0f) - mu * mu;
            float rs = rsqrtf(var + LN_EPS);
            int r = ty * 4 + i;
            float o[8];
#pragma unroll
            for (int j = 0; j < 8; j++) o[j] = tanhf((v[j] - mu) * rs * gam[j] + bet[j]);
            float4* dst = (float4*)&Xs[r * 132 + tx * 8];
            dst[0] = make_float4(o[0], o[1], o[2], o[3]);
            dst[1] = make_float4(o[4], o[5], o[6], o[7]);
        }
    }

    // ---- phase 2: gi = Xs @ Wih^T + b ----
    for (int j0t = 0; j0t < 4; j0t++) {
        const int j0 = j0t * 128;
        ull acc2[4][4];
#pragma unroll
        for (int i = 0; i < 4; i++)
#pragma unroll
            for (int j = 0; j < 4; j++) acc2[i][j] = 0ull;

        for (int kt = 0; kt < 4; kt++) {
            __syncthreads();
            const int kb = kt * 32;
#pragma unroll
            for (int s = 0; s < 16; s++) {
                int idx = tid + s * 256;
                int kk = idx & 31, j = idx >> 5;
                Bs[kk * 132 + j] = Wih[(j0 + j) * HDIM + kb + kk];
            }
            __syncthreads();
            if (wactive) {
#pragma unroll 8
                for (int kk = 0; kk < 32; kk++) {
                    ull a2[4];
#pragma unroll
                    for (int i = 0; i < 4; i++) {
                        float a = Xs[(ty * 4 + i) * 132 + kb + kk];
                        a2[i] = pack2(a, a);
                    }
                    ulonglong2 b01 = *(const ulonglong2*)&Bs[kk * 132 + tx * 8];
                    ulonglong2 b23 = *(const ulonglong2*)&Bs[kk * 132 + tx * 8 + 4];
#pragma unroll
                    for (int i = 0; i < 4; i++) {
                        acc2[i][0] = fma2(a2[i], b01.x, acc2[i][0]);
                        acc2[i][1] = fma2(a2[i], b01.y, acc2[i][1]);
                        acc2[i][2] = fma2(a2[i], b23.x, acc2[i][2]);
                        acc2[i][3] = fma2(a2[i], b23.y, acc2[i][3]);
                    }
                }
            }
        }
        if (wactive) {
            float bs[8];
#pragma unroll
            for (int j = 0; j < 8; j++) {
                int jj = j0 + tx * 8 + j;
                bs[j] = bih[jj] + bhh[jj];
            }
#pragma unroll
            for (int i = 0; i < 4; i++) {
                int r = ty * 4 + i;
                int t = r & 31, p = r >> 5;
                if (t < len2[p]) {
                    float v[8];
#pragma unroll
                    for (int pp = 0; pp < 4; pp++) {
                        float2 u = unpack2(acc2[i][pp]);
                        v[2 * pp] = u.x; v[2 * pp + 1] = u.y;
                    }
                    size_t base = ((size_t)(blockIdx.x * 2 + p) * LMAX + t) * G4 + j0 + tx * 8;
                    float4* dst = (float4*)&g_gi[base];
                    dst[0] = make_float4(v[0] + bs[0], v[1] + bs[1], v[2] + bs[2], v[3] + bs[3]);
                    dst[1] = make_float4(v[4] + bs[4], v[5] + bs[5], v[6] + bs[6], v[7] + bs[7]);
                }
            }
        }
    }
}

// ---------------- kernel 2: LSTM recurrence ----------------
// 32 paths/block, 256 threads: ty owns 4 rows, tx owns 4 cols per gate.
// Inner loop: fma.rn.f32x2 (2 cols per op).
__global__ void __launch_bounds__(256, 2) k_lstm(const int* __restrict__ lens) {
    extern __shared__ float sm[];
    float* hs = sm;                 // 32*132
    float* Bs = sm + 32 * 132;      // 32*520
    __shared__ int ln_s[32];
    __shared__ int maxlen_s;

    const int tid = threadIdx.x;
    const int tx = tid & 31, ty = tid >> 5;
    const int n0 = blockIdx.x * 32;

#pragma unroll
    for (int s = 0; s < 16; s++) {
        int idx = tid + s * 256;
        int n = idx >> 7, k = idx & 127;
        hs[n * 132 + k] = 0.0f;
    }
    if (tid < 32) {
        int l = lens[n0 + tid];
        ln_s[tid] = l;
#pragma unroll
        for (int m = 16; m >= 1; m >>= 1) l = max(l, __shfl_xor_sync(0xffffffffu, l, m));
        if (tid == 0) maxlen_s = l;
    }
    __syncthreads();

    int myln[4];
    int mymax = 0;
#pragma unroll
    for (int i = 0; i < 4; i++) { myln[i] = ln_s[4 * ty + i]; mymax = max(mymax, myln[i]); }
    const int blkmax = maxlen_s;

    float c[4][4];
#pragma unroll
    for (int i = 0; i < 4; i++)
#pragma unroll
        for (int j = 0; j < 4; j++) c[i][j] = 0.0f;

    for (int t = 0; t < blkmax; t++) {
        ull acc[4][4][2];
#pragma unroll
        for (int i = 0; i < 4; i++)
#pragma unroll
            for (int q = 0; q < 4; q++) { acc[i][q][0] = 0ull; acc[i][q][1] = 0ull; }

        const bool active = (t < mymax);

        for (int kt = 0; kt < 4; kt++) {
            __syncthreads();
#pragma unroll
            for (int s = 0; s < 16; s++) {
                int f4 = tid + s * 256;
                int kk = f4 >> 7;
                int col = (f4 & 127) * 4;
                *(float4*)&Bs[kk * 520 + col] =
                    *(const float4*)&g_WhhT[(kt * 32 + kk) * G4 + col];
            }
            __syncthreads();
            if (active) {
                const int kb = kt * 32;
#pragma unroll 8
                for (int kk = 0; kk < 32; kk++) {
                    ull a2[4];
#pragma unroll
                    for (int i = 0; i < 4; i++) {
                        float a = hs[(4 * ty + i) * 132 + kb + kk];
                        a2[i] = pack2(a, a);
                    }
#pragma unroll
                    for (int q = 0; q < 4; q++) {
                        ulonglong2 b = *(const ulonglong2*)&Bs[kk * 520 + q * 128 + tx * 4];
#pragma unroll
                        for (int i = 0; i < 4; i++) {
                            acc[i][q][0] = fma2(a2[i], b.x, acc[i][q][0]);
                            acc[i][q][1] = fma2(a2[i], b.y, acc[i][q][1]);
                        }
                    }
                }
            }
        }

        if (active) {
#pragma unroll
            for (int i = 0; i < 4; i++) {
                int n = 4 * ty + i;
                if (t < myln[i]) {
                    size_t base = ((size_t)(n0 + n) * LMAX + t) * G4 + tx * 4;
                    float4 gi = *(const float4*)&g_gi[base];
                    float4 gf = *(const float4*)&g_gi[base + 128];
                    float4 gg = *(const float4*)&g_gi[base + 256];
                    float4 go = *(const float4*)&g_gi[base + 384];
                    float2 i0 = unpack2(acc[i][0][0]), i1 = unpack2(acc[i][0][1]);
                    float2 f0 = unpack2(acc[i][1][0]), f1 = unpack2(acc[i][1][1]);
                    float2 g0 = unpack2(acc[i][2][0]), g1 = unpack2(acc[i][2][1]);
                    float2 o0 = unpack2(acc[i][3][0]), o1 = unpack2(acc[i][3][1]);
                    float xi[4] = {gi.x + i0.x, gi.y + i0.y, gi.z + i1.x, gi.w + i1.y};
                    float xf[4] = {gf.x + f0.x, gf.y + f0.y, gf.z + f1.x, gf.w + f1.y};
                    float xg[4] = {gg.x + g0.x, gg.y + g0.y, gg.z + g1.x, gg.w + g1.y};
                    float xo[4] = {go.x + o0.x, go.y + o0.y, go.z + o1.x, go.w + o1.y};
                    float h4[4];
#pragma unroll
                    for (int j = 0; j < 4; j++) {
                        float cn = sigm(xf[j]) * c[i][j] + sigm(xi[j]) * tanhf(xg[j]);
                        c[i][j] = cn;
                        h4[j] = sigm(xo[j]) * tanhf(cn);
                    }
                    *(float4*)&hs[n * 132 + tx * 4] = make_float4(h4[0], h4[1], h4[2], h4[3]);
                }
            }
            __syncwarp();
        }
    }

    __syncwarp();
#pragma unroll
    for (int i = 0; i < 4; i++) {
        int n = 4 * ty + i;
        *(float4*)&g_h[(size_t)(n0 + n) * HDIM + tx * 4] = *(const float4*)&hs[n * 132 + tx * 4];
    }
}

// ---------------- kernel 3a: init accumulators ----------------
__global__ void k_init() {
    int i = blockIdx.x * blockDim.x + threadIdx.x;
    if (i < GRP * HDIM) g_wsum[i] = 0.0f;
    if (i < GRP) {
        g_gsum[i] = 0.0f;
        g_cnt[i] = 0.0f;
        g_gmax[i] = 0u;
    }
}

// ---------------- kernel 3b: attention logits + segment max ----------------
__global__ void __launch_bounds__(256) k_logits(const float* __restrict__ ap,
                                                const int* __restrict__ seg) {
    int w = threadIdx.x >> 5, lane = threadIdx.x & 31;
    int n = blockIdx.x * 8 + w;
    float s = 0.0f;
#pragma unroll
    for (int q = 0; q < 4; q++) s += g_h[n * HDIM + lane + 32 * q] * ap[lane + 32 * q];
#pragma unroll
    for (int m = 16; m >= 1; m >>= 1) s += __shfl_xor_sync(0xffffffffu, s, m);
    if (lane == 0) {
        g_logits[n] = s;
        atomicMax(&g_gmax[seg[n]], enc_f(s));
    }
}

// ---------------- kernel 3c: exp + segment sum + count ----------------
__global__ void __launch_bounds__(256) k_expsum(const int* __restrict__ seg) {
    int n = blockIdx.x * 256 + threadIdx.x;
    int g = seg[n];
    float e = expf(g_logits[n] - dec_f(g_gmax[g]));
    g_e[n] = e;
    atomicAdd(&g_gsum[g], e);
    atomicAdd(&g_cnt[g], 1.0f);
}

// ---------------- kernel 3d: weighted hidden sum per group ----------------
__global__ void __launch_bounds__(256) k_wsum(const int* __restrict__ seg) {
    int w = threadIdx.x >> 5, lane = threadIdx.x & 31;
    int n = blockIdx.x * 8 + w;
    float e = g_e[n];
    int g = seg[n];
#pragma unroll
    for (int q = 0; q < 4; q++)
        atomicAdd(&g_wsum[g * HDIM + lane + 32 * q], e * g_h[n * HDIM + lane + 32 * q]);
}

// ---------------- kernel 4: head ----------------
__global__ void __launch_bounds__(256) k_head(const float* __restrict__ W_out,
                                              const float* __restrict__ W_cls,
                                              const float* __restrict__ ap,
                                              float* __restrict__ out,
                                              int out_size) {
    __shared__ float cs[16 * 128];
    __shared__ float cvs[16 * 128];
    const int tid = threadIdx.x;
    const int g0 = blockIdx.x * 16;
    const bool full = (out_size >= 2048 + GRP * HDIM + HDIM);

#pragma unroll
    for (int s = 0; s < 8; s++) {
        int idx = tid + s * 256;
        int gg = idx >> 7, k = idx & 127;
        int gi = g0 + gg;
        cs[gg * 128 + k] = g_wsum[gi * HDIM + k] / (g_gsum[gi] * g_cnt[gi]);
    }
    __syncthreads();

    int row = tid >> 4;
    int c0 = (tid & 15) * 8;
    float acc[8];
#pragma unroll
    for (int j = 0; j < 8; j++) acc[j] = 0.0f;
    for (int k = 0; k < 128; k++) {
        float a = cs[row * 128 + k];
#pragma unroll
        for (int j = 0; j < 8; j++) acc[j] += a * W_out[(c0 + j) * 128 + k];
    }
#pragma unroll
    for (int j = 0; j < 8; j++) {
        cvs[row * 128 + c0 + j] = acc[j];
        if (full) out[2048 + (g0 + row) * 128 + c0 + j] = acc[j];
    }
    __syncthreads();

    if (tid < 32) {
        int r = tid >> 1, c = tid & 1;
        float s = 0.0f;
        for (int k = 0; k < 128; k++) s += cvs[r * 128 + k] * W_cls[c * 128 + k];
        out[(g0 + r) * 2 + c] = s;
    }
    if (full && blockIdx.x == 0 && tid < 128) out[2048 + GRP * HDIM + tid] = ap[tid];
}

// ---------------- launch ----------------
extern "C" void kernel_launch(void* const* d_in, const int* in_sizes, int n_in,
                              void* d_out, int out_size) {
    const float* inputs = (const float*)d_in[0];
    const int* lens     = (const int*)d_in[1];
    const int* seg      = (const int*)d_in[2];
    const float* W_in   = (const float*)d_in[3];
    const float* gamma  = (const float*)d_in[4];
    const float* beta   = (const float*)d_in[5];
    const float* Wih    = (const float*)d_in[6];
    const float* Whh    = (const float*)d_in[7];
    const float* bih    = (const float*)d_in[8];
    const float* bhh    = (const float*)d_in[9];
    const float* ap     = (const float*)d_in[10];
    const float* W_out  = (const float*)d_in[11];
    const float* W_cls  = (const float*)d_in[12];
    float* out = (float*)d_out;

    const int fp_smem   = (64 * 33 + 32 * 132 + 64 * 132) * 4;   // 59136 B
    const int lstm_smem = (32 * 132 + 32 * 520) * 4;             // 83456 B
    cudaFuncSetAttribute(k_fp, cudaFuncAttributeMaxDynamicSharedMemorySize, fp_smem);
    cudaFuncSetAttribute(k_lstm, cudaFuncAttributeMaxDynamicSharedMemorySize, lstm_smem);

    k_tw<<<256, 256>>>(Whh);
    k_fp<<<RTOT / 64, 256, fp_smem>>>(inputs, W_in, gamma, beta, Wih, bih, bhh, lens);
    k_lstm<<<NPATH / 32, 256, lstm_smem>>>(lens);
    k_init<<<(GRP * HDIM + 255) / 256, 256>>>();
    k_logits<<<NPATH / 8, 256>>>(ap, seg);
    k_expsum<<<NPATH / 256, 256>>>(seg);
    k_wsum<<<NPATH / 8, 256>>>(seg);
    k_head<<<GRP / 16, 256>>>(W_out, W_cls, ap, out, out_size);
}